// round 3
// baseline (speedup 1.0000x reference)
#include <cuda_runtime.h>
#include <cuda_bf16.h>

// ANFIS fused kernel for GB300 (sm_103a).
//
// Reference math:
//   mem[b,f,m] = exp(-((x[b,f]-mean[f,m])/sigma[f,m])^2)
//   fs[b, i*M+j] = mem[b,0,i] * mem[b,1,j]        (F=2, R=M*M)
//   norm = fs / sum_r fs  ;  sum_r fs = S0*S1 (separable!)
//   cons[b,r] = x0*cw[r,0] + x1*cw[r,1] + cb[r]
//   out[b] = sum_r cons*norm
//
// Restructured:
//   nm0[b,i] = mem0/S0, nm1[b,j] = mem1/S1
//   out[b] = sum_{i,j} nm0[b,i]*nm1[b,j]*(x0*cw0[i,j]+x1*cw1[i,j]+cb[i,j])
//
// 3 kernels: membership+normalize -> bilinear reduction (batch-tiled for
// weight reuse) -> deterministic final sum over i-tiles.

#define M_MF 512
#define B_SZ 256
#define TI   8            // i-rows per block
#define TB   16           // batches per block
#define NIT  (M_MF / TI)  // 64 i-tiles
#define NBT  (B_SZ / TB)  // 16 batch-tiles
#define THREADS 256

__device__ float g_nm0[B_SZ * M_MF];
__device__ float g_nm1[B_SZ * M_MF];
__device__ float g_scratch[B_SZ * NIT];

// ---------------------------------------------------------------------------
// Kernel 1: membership functions + per-(b,f) normalization.
// One block per batch, 512 threads (one per membership function).
// ---------------------------------------------------------------------------
__global__ void __launch_bounds__(M_MF) memb_kernel(
    const float* __restrict__ x,
    const float* __restrict__ mean,
    const float* __restrict__ sigma)
{
    __shared__ float red[M_MF];
    const int b = blockIdx.x;
    const int m = threadIdx.x;

    const float x0 = x[b * 2 + 0];
    const float x1 = x[b * 2 + 1];

    float d0 = (x0 - mean[m]) / sigma[m];
    float e0 = __expf(-d0 * d0);
    float d1 = (x1 - mean[M_MF + m]) / sigma[M_MF + m];
    float e1 = __expf(-d1 * d1);

    // reduce S0
    red[m] = e0;
    __syncthreads();
    #pragma unroll
    for (int s = M_MF / 2; s > 0; s >>= 1) {
        if (m < s) red[m] += red[m + s];
        __syncthreads();
    }
    const float S0 = red[0];
    __syncthreads();

    // reduce S1
    red[m] = e1;
    __syncthreads();
    #pragma unroll
    for (int s = M_MF / 2; s > 0; s >>= 1) {
        if (m < s) red[m] += red[m + s];
        __syncthreads();
    }
    const float S1 = red[0];

    g_nm0[b * M_MF + m] = e0 / S0;
    g_nm1[b * M_MF + m] = e1 / S1;
}

// ---------------------------------------------------------------------------
// Kernel 2: bilinear reduction.
// Grid (NIT, NBT). Each block: TI i-rows x TB batches x all 512 j.
// Thread tid owns columns {tid, tid+256}. cw/cb loaded once per block from
// L2 into registers and reused across TB batches (key bandwidth amplifier).
// ---------------------------------------------------------------------------
__global__ void __launch_bounds__(THREADS) rule_kernel(
    const float* __restrict__ x,
    const float* __restrict__ cw,
    const float* __restrict__ cb)
{
    __shared__ float sx0[TB];
    __shared__ float sx1[TB];
    __shared__ float s_nm0[TB][TI];
    __shared__ float s_part[TB][8];

    const int tid = threadIdx.x;
    const int it  = blockIdx.x;   // i-tile
    const int bt  = blockIdx.y;   // batch-tile
    const int i0  = it * TI;
    const int b0  = bt * TB;

    if (tid < TB) {
        sx0[tid] = x[(b0 + tid) * 2 + 0];
        sx1[tid] = x[(b0 + tid) * 2 + 1];
    }
    if (tid < TB * TI) {
        const int lb = tid / TI;
        const int ii = tid % TI;
        s_nm0[lb][ii] = g_nm0[(b0 + lb) * M_MF + i0 + ii];
    }

    float m1a[TB], m1b[TB], acc[TB];
    #pragma unroll
    for (int lb = 0; lb < TB; ++lb) {
        m1a[lb] = g_nm1[(b0 + lb) * M_MF + tid];
        m1b[lb] = g_nm1[(b0 + lb) * M_MF + tid + 256];
        acc[lb] = 0.0f;
    }
    __syncthreads();

    const float2* __restrict__ cw2 = (const float2*)cw;

    #pragma unroll
    for (int i = 0; i < TI; ++i) {
        const int ri = (i0 + i) * M_MF;
        // weights for this i-row: loaded once, reused across TB batches
        const float2 ca  = cw2[ri + tid];        // (cw0, cw1) at j = tid
        const float2 cbv = cw2[ri + tid + 256];  // (cw0, cw1) at j = tid+256
        const float  cbA = cb[ri + tid];
        const float  cbB = cb[ri + tid + 256];
        #pragma unroll
        for (int lb = 0; lb < TB; ++lb) {
            const float x0 = sx0[lb];
            const float x1 = sx1[lb];
            const float w  = s_nm0[lb][i];
            const float consA = fmaf(x0, ca.x,  fmaf(x1, ca.y,  cbA));
            const float consB = fmaf(x0, cbv.x, fmaf(x1, cbv.y, cbB));
            acc[lb] = fmaf(w, fmaf(m1a[lb], consA, m1b[lb] * consB), acc[lb]);
        }
    }

    // Deterministic block reduction: warp shuffle, then cross-warp in smem.
    const int lane = tid & 31;
    const int wrp  = tid >> 5;
    #pragma unroll
    for (int lb = 0; lb < TB; ++lb) {
        float v = acc[lb];
        v += __shfl_down_sync(0xFFFFFFFFu, v, 16);
        v += __shfl_down_sync(0xFFFFFFFFu, v, 8);
        v += __shfl_down_sync(0xFFFFFFFFu, v, 4);
        v += __shfl_down_sync(0xFFFFFFFFu, v, 2);
        v += __shfl_down_sync(0xFFFFFFFFu, v, 1);
        if (lane == 0) s_part[lb][wrp] = v;
    }
    __syncthreads();

    if (tid < TB) {
        float s = 0.0f;
        #pragma unroll
        for (int w = 0; w < 8; ++w) s += s_part[tid][w];
        g_scratch[(b0 + tid) * NIT + it] = s;
    }
}

// ---------------------------------------------------------------------------
// Kernel 3: deterministic final sum over the 64 i-tile partials per batch.
// ---------------------------------------------------------------------------
__global__ void __launch_bounds__(B_SZ) final_kernel(float* __restrict__ out)
{
    const int b = threadIdx.x;
    float s = 0.0f;
    #pragma unroll
    for (int it = 0; it < NIT; ++it) s += g_scratch[b * NIT + it];
    out[b] = s;
}

// ---------------------------------------------------------------------------
extern "C" void kernel_launch(void* const* d_in, const int* in_sizes, int n_in,
                              void* d_out, int out_size)
{
    const float* x     = (const float*)d_in[0];   // [B, 2]
    const float* mean  = (const float*)d_in[1];   // [2, M]
    const float* sigma = (const float*)d_in[2];   // [2, M]
    const float* cw    = (const float*)d_in[3];   // [R, 2]
    const float* cb    = (const float*)d_in[4];   // [R, 1]
    float* out = (float*)d_out;                   // [B, 1]

    memb_kernel<<<B_SZ, M_MF>>>(x, mean, sigma);
    rule_kernel<<<dim3(NIT, NBT), THREADS>>>(x, cw, cb);
    final_kernel<<<1, B_SZ>>>(out);
}

// round 4
// speedup vs baseline: 1.2116x; 1.2116x over previous
#include <cuda_runtime.h>
#include <cuda_bf16.h>

// ANFIS fused kernel for GB300 (sm_103a) — round 3.
//
//   nm0[b,i] = mem0/S0, nm1[b,j] = mem1/S1
//   out[b] = sum_{i,j} nm0[b,i]*nm1[b,j]*(x0*cw0[i,j]+x1*cw1[i,j]+cb[i,j])
//
// R3 changes vs R1:
//   - memb_kernel: warp-shuffle reductions (2 barriers instead of 18).
//   - rule_kernel: packed fp32x2 math (fma.rn.f32x2) over batch PAIRS.
//     1.75 packed ops per rule-element vs 3.5 scalar FFMA -> ~2x fma-pipe.

#define M_MF 512
#define B_SZ 256
#define TI   8            // i-rows per block
#define TB   16           // batches per block
#define NP   (TB / 2)     // 8 batch pairs
#define NIT  (M_MF / TI)  // 64 i-tiles
#define NBT  (B_SZ / TB)  // 16 batch-tiles
#define THREADS 256

__device__ float g_nm0[B_SZ * M_MF];
__device__ float g_nm1[B_SZ * M_MF];
__device__ float g_scratch[B_SZ * NIT];

// ---------------------------------------------------------------------------
// Packed f32x2 helpers (Blackwell sm_103a). ptxas never auto-fuses these;
// they must come from PTX directly.
// ---------------------------------------------------------------------------
typedef unsigned long long u64;

__device__ __forceinline__ u64 pack2(float a, float b) {
    u64 r; asm("mov.b64 %0, {%1, %2};" : "=l"(r) : "f"(a), "f"(b)); return r;
}
__device__ __forceinline__ u64 fma2(u64 a, u64 b, u64 c) {
    u64 r; asm("fma.rn.f32x2 %0, %1, %2, %3;" : "=l"(r) : "l"(a), "l"(b), "l"(c)); return r;
}
__device__ __forceinline__ u64 mul2(u64 a, u64 b) {
    u64 r; asm("mul.rn.f32x2 %0, %1, %2;" : "=l"(r) : "l"(a), "l"(b)); return r;
}
__device__ __forceinline__ void unpack2(u64 a, float& lo, float& hi) {
    asm("mov.b64 {%0, %1}, %2;" : "=f"(lo), "=f"(hi) : "l"(a));
}

// ---------------------------------------------------------------------------
// Kernel 1: membership functions + per-(b,f) normalization.
// One block per batch, 512 threads. Warp-shuffle reduction, 2 barriers.
// ---------------------------------------------------------------------------
__global__ void __launch_bounds__(M_MF) memb_kernel(
    const float* __restrict__ x,
    const float* __restrict__ mean,
    const float* __restrict__ sigma)
{
    __shared__ float s0[16], s1[16];
    const int b    = blockIdx.x;
    const int m    = threadIdx.x;
    const int lane = m & 31;
    const int wrp  = m >> 5;

    const float x0 = x[b * 2 + 0];
    const float x1 = x[b * 2 + 1];

    const float d0 = (x0 - mean[m]) * __fdividef(1.0f, sigma[m]);
    const float e0 = __expf(-d0 * d0);
    const float d1 = (x1 - mean[M_MF + m]) * __fdividef(1.0f, sigma[M_MF + m]);
    const float e1 = __expf(-d1 * d1);

    float r0 = e0, r1 = e1;
    #pragma unroll
    for (int off = 16; off > 0; off >>= 1) {
        r0 += __shfl_down_sync(0xFFFFFFFFu, r0, off);
        r1 += __shfl_down_sync(0xFFFFFFFFu, r1, off);
    }
    if (lane == 0) { s0[wrp] = r0; s1[wrp] = r1; }
    __syncthreads();

    if (m < 32) {
        float v0 = (lane < 16) ? s0[lane] : 0.0f;
        float v1 = (lane < 16) ? s1[lane] : 0.0f;
        #pragma unroll
        for (int off = 8; off > 0; off >>= 1) {
            v0 += __shfl_down_sync(0xFFFFFFFFu, v0, off);
            v1 += __shfl_down_sync(0xFFFFFFFFu, v1, off);
        }
        if (lane == 0) { s0[0] = v0; s1[0] = v1; }
    }
    __syncthreads();

    const float invS0 = __fdividef(1.0f, s0[0]);
    const float invS1 = __fdividef(1.0f, s1[0]);
    g_nm0[b * M_MF + m] = e0 * invS0;
    g_nm1[b * M_MF + m] = e1 * invS1;
}

// ---------------------------------------------------------------------------
// Kernel 2: bilinear reduction, packed f32x2 over batch pairs.
// Grid (NIT, NBT). Thread tid owns j columns {tid, tid+256}.
// ---------------------------------------------------------------------------
__global__ void __launch_bounds__(THREADS) rule_kernel(
    const float* __restrict__ x,
    const float* __restrict__ cw,
    const float* __restrict__ cb)
{
    __shared__ float sx[TB * 2];            // x staged: [lb*2 + f]
    __shared__ float s_w[TI][TB];           // nm0, pair-contiguous in b
    __shared__ float s_part[TB][8];

    const int tid = threadIdx.x;
    const int it  = blockIdx.x;
    const int bt  = blockIdx.y;
    const int i0  = it * TI;
    const int b0  = bt * TB;

    if (tid < TB * 2) sx[tid] = x[b0 * 2 + tid];
    if (tid < TB * TI) {
        const int lb = tid / TI;
        const int ii = tid % TI;
        s_w[ii][lb] = g_nm0[(b0 + lb) * M_MF + i0 + ii];
    }

    // nm1 packed per batch pair for this thread's two columns
    u64 m1a[NP], m1b[NP], acc[NP];
    #pragma unroll
    for (int lp = 0; lp < NP; ++lp) {
        const int ba = b0 + 2 * lp;
        m1a[lp] = pack2(g_nm1[ba * M_MF + tid],       g_nm1[(ba + 1) * M_MF + tid]);
        m1b[lp] = pack2(g_nm1[ba * M_MF + tid + 256], g_nm1[(ba + 1) * M_MF + tid + 256]);
        acc[lp] = 0ull;
    }
    __syncthreads();

    // x packed per batch pair (registers, i-invariant)
    u64 x0p[NP], x1p[NP];
    #pragma unroll
    for (int lp = 0; lp < NP; ++lp) {
        x0p[lp] = pack2(sx[(2 * lp) * 2 + 0], sx[(2 * lp + 1) * 2 + 0]);
        x1p[lp] = pack2(sx[(2 * lp) * 2 + 1], sx[(2 * lp + 1) * 2 + 1]);
    }

    const float2* __restrict__ cw2 = (const float2*)cw;

    #pragma unroll
    for (int i = 0; i < TI; ++i) {
        const int ri = (i0 + i) * M_MF;
        const float2 ca  = cw2[ri + tid];
        const float2 cbv = cw2[ri + tid + 256];
        const float  cA  = cb[ri + tid];
        const float  cB  = cb[ri + tid + 256];
        // duplicate-pack the weights once per i (shared across all batches)
        const u64 caxp = pack2(ca.x,  ca.x);
        const u64 cayp = pack2(ca.y,  ca.y);
        const u64 cAp  = pack2(cA,    cA);
        const u64 cbxp = pack2(cbv.x, cbv.x);
        const u64 cbyp = pack2(cbv.y, cbv.y);
        const u64 cBp  = pack2(cB,    cB);

        #pragma unroll
        for (int lp = 0; lp < NP; ++lp) {
            const u64 consA = fma2(x0p[lp], caxp, fma2(x1p[lp], cayp, cAp));
            const u64 consB = fma2(x0p[lp], cbxp, fma2(x1p[lp], cbyp, cBp));
            const u64 inner = fma2(m1a[lp], consA, mul2(m1b[lp], consB));
            const u64 wp    = *(const u64*)&s_w[i][2 * lp];   // 8B-aligned LDS.64
            acc[lp]         = fma2(wp, inner, acc[lp]);
        }
    }

    // Deterministic block reduction per batch.
    const int lane = tid & 31;
    const int wrp  = tid >> 5;
    #pragma unroll
    for (int lp = 0; lp < NP; ++lp) {
        float v0, v1;
        unpack2(acc[lp], v0, v1);
        #pragma unroll
        for (int off = 16; off > 0; off >>= 1) {
            v0 += __shfl_down_sync(0xFFFFFFFFu, v0, off);
            v1 += __shfl_down_sync(0xFFFFFFFFu, v1, off);
        }
        if (lane == 0) { s_part[2 * lp][wrp] = v0; s_part[2 * lp + 1][wrp] = v1; }
    }
    __syncthreads();

    if (tid < TB) {
        float s = 0.0f;
        #pragma unroll
        for (int w = 0; w < 8; ++w) s += s_part[tid][w];
        g_scratch[(b0 + tid) * NIT + it] = s;
    }
}

// ---------------------------------------------------------------------------
// Kernel 3: deterministic final sum over the 64 i-tile partials per batch.
// ---------------------------------------------------------------------------
__global__ void __launch_bounds__(B_SZ) final_kernel(float* __restrict__ out)
{
    const int b = threadIdx.x;
    float s = 0.0f;
    #pragma unroll
    for (int it = 0; it < NIT; ++it) s += g_scratch[b * NIT + it];
    out[b] = s;
}

// ---------------------------------------------------------------------------
extern "C" void kernel_launch(void* const* d_in, const int* in_sizes, int n_in,
                              void* d_out, int out_size)
{
    const float* x     = (const float*)d_in[0];   // [B, 2]
    const float* mean  = (const float*)d_in[1];   // [2, M]
    const float* sigma = (const float*)d_in[2];   // [2, M]
    const float* cw    = (const float*)d_in[3];   // [R, 2]
    const float* cb    = (const float*)d_in[4];   // [R, 1]
    float* out = (float*)d_out;                   // [B, 1]

    memb_kernel<<<B_SZ, M_MF>>>(x, mean, sigma);
    rule_kernel<<<dim3(NIT, NBT), THREADS>>>(x, cw, cb);
    final_kernel<<<1, B_SZ>>>(out);
}